// round 5
// baseline (speedup 1.0000x reference)
#include <cuda_runtime.h>
#include <cuda_bf16.h>
#include <cstdint>

#define HID 1024
#define MROWS 32768
#define STAGE 40960
#define NSTAGE 4
#define DSMEM_TOTAL (NSTAGE * STAGE)

// ---- static device scratch (allocation-free rule) ----
__device__ __align__(16) __nv_bfloat16 g_x_hi [(size_t)MROWS * 512];
__device__ __align__(16) __nv_bfloat16 g_x_lo [(size_t)MROWS * 512];
__device__ __align__(16) __nv_bfloat16 g_w_hi [(size_t)3 * HID * 512];
__device__ __align__(16) __nv_bfloat16 g_w_lo [(size_t)3 * HID * 512];
__device__ __align__(16) __nv_bfloat16 g_WH_hi[(size_t)5 * HID * HID];
__device__ __align__(16) __nv_bfloat16 g_WH_lo[(size_t)5 * HID * HID];
__device__ __align__(16) __nv_bfloat16 g_WT_hi[(size_t)5 * HID * HID];
__device__ __align__(16) __nv_bfloat16 g_WT_lo[(size_t)5 * HID * HID];
__device__ __align__(16) __nv_bfloat16 g_WC_hi[(size_t)5 * HID * HID];
__device__ __align__(16) __nv_bfloat16 g_WC_lo[(size_t)5 * HID * HID];
__device__ __align__(16) __nv_bfloat16 g_hA_hi[(size_t)MROWS * HID];
__device__ __align__(16) __nv_bfloat16 g_hA_lo[(size_t)MROWS * HID];
__device__ __align__(16) __nv_bfloat16 g_hB_hi[(size_t)MROWS * HID];
__device__ __align__(16) __nv_bfloat16 g_hB_lo[(size_t)MROWS * HID];

// ---- helpers ----
__device__ __forceinline__ uint32_t smem_u32(const void* p) {
    uint32_t a;
    asm("{ .reg .u64 t; cvta.to.shared.u64 t, %1; cvt.u32.u64 %0, t; }" : "=r"(a) : "l"(p));
    return a;
}
__device__ __forceinline__ void cpa16(uint32_t s, const void* g) {
    asm volatile("cp.async.cg.shared.global [%0], [%1], 16;" :: "r"(s), "l"(g));
}
__device__ __forceinline__ void cpa_commit() {
    asm volatile("cp.async.commit_group;" ::: "memory");
}
__device__ __forceinline__ void cpa_wait2() {
    asm volatile("cp.async.wait_group 2;" ::: "memory");
}
__device__ __forceinline__ void ldsm4(uint32_t* r, uint32_t a) {
    asm volatile("ldmatrix.sync.aligned.m8n8.x4.shared.b16 {%0,%1,%2,%3}, [%4];"
                 : "=r"(r[0]), "=r"(r[1]), "=r"(r[2]), "=r"(r[3]) : "r"(a));
}
__device__ __forceinline__ void mma16816(float* d, const uint32_t* a, uint32_t b0, uint32_t b1) {
    asm volatile(
        "mma.sync.aligned.m16n8k16.row.col.f32.bf16.bf16.f32 "
        "{%0,%1,%2,%3}, {%4,%5,%6,%7}, {%8,%9}, {%0,%1,%2,%3};"
        : "+f"(d[0]), "+f"(d[1]), "+f"(d[2]), "+f"(d[3])
        : "r"(a[0]), "r"(a[1]), "r"(a[2]), "r"(a[3]), "r"(b0), "r"(b1));
}
// swizzled byte offset of 16B chunk (row r, chunk c in 0..3) in a 64/128-row x k32 tile
__device__ __forceinline__ uint32_t swz(int r, int c) {
    return (uint32_t)((r >> 1) * 128 + (r & 1) * 64 + ((c ^ ((r >> 1) & 3)) << 4));
}
__device__ __forceinline__ float sigm_(float x) { return __fdividef(1.f, 1.f + __expf(-x)); }
__device__ __forceinline__ float tanh_(float x) {
    float ax = fabsf(x), e = __expf(-2.f * ax);
    float t = __fdividef(1.f - e, 1.f + e);
    return x >= 0.f ? t : -t;
}
__device__ __forceinline__ float bf2f(uint32_t b) { return __uint_as_float(b << 16); }
__device__ __forceinline__ uint32_t f2bf(float f) {
    return (uint32_t)__bfloat16_as_ushort(__float2bfloat16(f));
}

// ---- split fp32 -> (hi, lo) bf16 ----
__global__ void split4(const float4* __restrict__ src, uint2* __restrict__ hi,
                       uint2* __restrict__ lo, int n4) {
    int i = blockIdx.x * blockDim.x + threadIdx.x;
    if (i >= n4) return;
    float4 v = src[i];
    float vv[4] = {v.x, v.y, v.z, v.w};
    uint32_t h[4], l[4];
#pragma unroll
    for (int k = 0; k < 4; k++) {
        h[k] = f2bf(vv[k]);
        l[k] = f2bf(vv[k] - bf2f(h[k]));
    }
    hi[i] = make_uint2(h[0] | (h[1] << 16), h[2] | (h[3] << 16));
    lo[i] = make_uint2(l[0] | (l[1] << 16), l[2] | (l[3] << 16));
}

// split three equal-size weight tensors in one launch (z selects tensor)
__global__ void split4w(const float4* __restrict__ s0, uint2* __restrict__ h0, uint2* __restrict__ l0,
                        const float4* __restrict__ s1, uint2* __restrict__ h1, uint2* __restrict__ l1,
                        const float4* __restrict__ s2, uint2* __restrict__ h2, uint2* __restrict__ l2,
                        int n4) {
    int i = blockIdx.x * blockDim.x + threadIdx.x;
    if (i >= n4) return;
    const float4* src = blockIdx.z == 0 ? s0 : (blockIdx.z == 1 ? s1 : s2);
    uint2* hi = blockIdx.z == 0 ? h0 : (blockIdx.z == 1 ? h1 : h2);
    uint2* lo = blockIdx.z == 0 ? l0 : (blockIdx.z == 1 ? l1 : l2);
    float4 v = src[i];
    float vv[4] = {v.x, v.y, v.z, v.w};
    uint32_t h[4], l[4];
#pragma unroll
    for (int k = 0; k < 4; k++) {
        h[k] = f2bf(vv[k]);
        l[k] = f2bf(vv[k] - bf2f(h[k]));
    }
    hi[i] = make_uint2(h[0] | (h[1] << 16), h[2] | (h[3] << 16));
    lo[i] = make_uint2(l[0] | (l[1] << 16), l[2] | (l[3] << 16));
}

// ---- fused 3-gate mma.sync GEMM + epilogue ----
// CTA tile: M=128, N=64 per gate, 3 gates. 512 threads, 16 warps in 4(m) x 4(n):
// wm = wid&3 (32 rows each, 2 x m16), wn = wid>>2 (16 cols each).
// smem stage: Ahi[0,8K) Alo[8K,16K) B[16K + (g*2+term)*4K), each tile k32-wide.
template<int KF, int MODE, int WSPLIT>
__global__ void __launch_bounds__(512, 1)
rhn_mma(const __nv_bfloat16* __restrict__ Ahi, const __nv_bfloat16* __restrict__ Alo,
        const __nv_bfloat16* __restrict__ B0hi, const __nv_bfloat16* __restrict__ B0lo,
        const __nv_bfloat16* __restrict__ B1hi, const __nv_bfloat16* __restrict__ B1lo,
        const __nv_bfloat16* __restrict__ B2hi, const __nv_bfloat16* __restrict__ B2lo,
        const float* __restrict__ e0, const float* __restrict__ e1, const float* __restrict__ e2,
        const __nv_bfloat16* __restrict__ hinHi, const __nv_bfloat16* __restrict__ hinLo,
        float* __restrict__ outF,
        __nv_bfloat16* __restrict__ outHi, __nv_bfloat16* __restrict__ outLo)
{
    constexpr int NK = KF / 32;
    extern __shared__ __align__(128) uint8_t smemraw[];
    const uint32_t sbase = smem_u32(smemraw);

    const int tid = threadIdx.x;
    const int lane = tid & 31;
    const int wid = tid >> 5;
    const int wm = wid & 3;
    const int wn = wid >> 2;
    const int m0 = blockIdx.y * 128;
    const int n0 = blockIdx.x * 64;

    // ---- producer mapping: 5 x 16B cp.async per thread per stage ----
    const char* gp[5];
    uint32_t so[5];
    {
        const int pr = tid >> 2;     // 0..127
        const int pc = tid & 3;      // 16B chunk in k32
        gp[0] = (const char*)(Ahi + (size_t)(m0 + pr) * KF + pc * 8);
        gp[1] = (const char*)(Alo + (size_t)(m0 + pr) * KF + pc * 8);
        so[0] = swz(pr, pc);
        so[1] = 8192u + swz(pr, pc);
        const __nv_bfloat16* bp[6] = {B0hi, B0lo, B1hi, B1lo, B2hi, B2lo};
#pragma unroll
        for (int j = 0; j < 3; j++) {
            int linear = j * 512 + tid;
            int bt = linear >> 8;            // 0..5
            int br = (linear >> 2) & 63;     // row in 64
            int bc = linear & 3;
            gp[2 + j] = (const char*)(bp[bt] + (size_t)(n0 + br) * KF + bc * 8);
            so[2 + j] = 16384u + bt * 4096u + swz(br, bc);
        }
    }

    // ---- consumer (ldmatrix) invariants ----
    const int mat = lane >> 3;
    const int khf = lane >> 4;
    uint32_t aln[2], bln;
    int asw[2], bsw;
#pragma unroll
    for (int mi = 0; mi < 2; mi++) {
        int r = wm * 32 + mi * 16 + (mat & 1) * 8 + (lane & 7);
        aln[mi] = (uint32_t)((r >> 1) * 128 + (r & 1) * 64);
        asw[mi] = (r >> 1) & 3;
    }
    {
        int r = wn * 16 + (mat & 1) * 8 + (lane & 7);
        bln = (uint32_t)((r >> 1) * 128 + (r & 1) * 64);
        bsw = (r >> 1) & 3;
    }

    float acc[3][2][2][4];
#pragma unroll
    for (int g = 0; g < 3; g++)
#pragma unroll
        for (int mi = 0; mi < 2; mi++)
#pragma unroll
            for (int nf = 0; nf < 2; nf++)
#pragma unroll
                for (int e = 0; e < 4; e++) acc[g][mi][nf][e] = 0.f;

#define ISSUE_STAGE(CH)                                                       \
    {                                                                         \
        uint32_t sb_ = sbase + ((CH) & 3) * STAGE;                            \
        size_t go_ = (size_t)(CH) * 64;                                       \
        _Pragma("unroll")                                                     \
        for (int j = 0; j < 5; j++) cpa16(sb_ + so[j], gp[j] + go_);          \
    }

    ISSUE_STAGE(0); cpa_commit();
    ISSUE_STAGE(1); cpa_commit();
    ISSUE_STAGE(2); cpa_commit();

    for (int i = 0; i < NK; i++) {
        cpa_wait2();
        __syncthreads();
        const uint32_t sb = sbase + (i & 3) * STAGE;

#pragma unroll
        for (int ks = 0; ks < 2; ks++) {
            const int c = ks * 2 + khf;
            uint32_t aH[8], aL[8];
#pragma unroll
            for (int mi = 0; mi < 2; mi++) {
                uint32_t off = aln[mi] + (uint32_t)((c ^ asw[mi]) << 4);
                ldsm4(&aH[mi * 4], sb + off);
                ldsm4(&aL[mi * 4], sb + 8192u + off);
            }
            const uint32_t boff = bln + (uint32_t)((c ^ bsw) << 4);
#pragma unroll
            for (int g = 0; g < 3; g++) {
                uint32_t bh[4], bl[4];
                ldsm4(bh, sb + 16384u + (g * 2 + 0) * 4096u + boff);
                ldsm4(bl, sb + 16384u + (g * 2 + 1) * 4096u + boff);
#pragma unroll
                for (int mi = 0; mi < 2; mi++) {
                    mma16816(acc[g][mi][0], &aH[mi * 4], bh[0], bh[2]);
                    mma16816(acc[g][mi][1], &aH[mi * 4], bh[1], bh[3]);
                    mma16816(acc[g][mi][0], &aH[mi * 4], bl[0], bl[2]);
                    mma16816(acc[g][mi][1], &aH[mi * 4], bl[1], bl[3]);
                    mma16816(acc[g][mi][0], &aL[mi * 4], bh[0], bh[2]);
                    mma16816(acc[g][mi][1], &aL[mi * 4], bh[1], bh[3]);
                }
            }
        }
        __syncthreads();
        if (i + 3 < NK) ISSUE_STAGE(i + 3);
        cpa_commit();   // keep wait_group accounting uniform
    }

    // ---- epilogue ----
    float bA[2][2], bB[2][2], bC2[2][2], bD[2][2];
#pragma unroll
    for (int nf = 0; nf < 2; nf++) {
        int n = n0 + wn * 16 + nf * 8 + (lane & 3) * 2;
        if (MODE == 0) {
            float2 i0 = *(const float2*)&e0[n],         h0 = *(const float2*)&e1[n];
            float2 i1 = *(const float2*)&e0[HID + n],   h1 = *(const float2*)&e1[HID + n];
            float2 i2 = *(const float2*)&e0[2*HID + n], h2 = *(const float2*)&e1[2*HID + n];
            bA[nf][0] = i0.x + h0.x; bA[nf][1] = i0.y + h0.y;
            bB[nf][0] = i1.x + h1.x; bB[nf][1] = i1.y + h1.y;
            bC2[nf][0] = i2.x;       bC2[nf][1] = i2.y;
            bD[nf][0] = h2.x;        bD[nf][1] = h2.y;
        } else {
            float2 v0 = *(const float2*)&e0[n];
            float2 v1 = *(const float2*)&e1[n];
            float2 v2 = *(const float2*)&e2[n];
            bA[nf][0] = v0.x; bA[nf][1] = v0.y;
            bB[nf][0] = v1.x; bB[nf][1] = v1.y;
            bC2[nf][0] = v2.x; bC2[nf][1] = v2.y;
        }
    }

#pragma unroll
    for (int mi = 0; mi < 2; mi++) {
#pragma unroll
        for (int half = 0; half < 2; half++) {
            const int m = m0 + wm * 32 + mi * 16 + (lane >> 2) + half * 8;
#pragma unroll
            for (int nf = 0; nf < 2; nf++) {
                const int n = n0 + wn * 16 + nf * 8 + (lane & 3) * 2;
                float res[2];
#pragma unroll
                for (int e = 0; e < 2; e++) {
                    float a0 = acc[0][mi][nf][half * 2 + e];
                    float a1 = acc[1][mi][nf][half * 2 + e];
                    float a2 = acc[2][mi][nf][half * 2 + e];
                    if (MODE == 0) {
                        float r = sigm_(a0 + bA[nf][e]);
                        float z = sigm_(a1 + bB[nf][e]);
                        float nn = tanh_(a2 + bC2[nf][e] + r * bD[nf][e]);
                        res[e] = (1.f - z) * nn;
                    } else {
                        float hh = tanh_(a0 + bA[nf][e]);
                        float t  = sigm_(a1 + bB[nf][e]);
                        float cc = sigm_(a2 + bC2[nf][e]);
                        uint32_t hw = *(const uint32_t*)(hinHi + (size_t)m * HID + n);
                        uint32_t lw = *(const uint32_t*)(hinLo + (size_t)m * HID + n);
                        float hv = (e == 0) ? (bf2f(hw & 0xFFFFu) + bf2f(lw & 0xFFFFu))
                                            : (bf2f(hw >> 16) + bf2f(lw >> 16));
                        res[e] = hh * t + hv * (1.f - cc);
                    }
                }
                if (WSPLIT) {
                    uint32_t h0 = f2bf(res[0]), h1 = f2bf(res[1]);
                    uint32_t l0 = f2bf(res[0] - bf2f(h0)), l1 = f2bf(res[1] - bf2f(h1));
                    *(uint32_t*)(outHi + (size_t)m * HID + n) = h0 | (h1 << 16);
                    *(uint32_t*)(outLo + (size_t)m * HID + n) = l0 | (l1 << 16);
                } else {
                    *(float2*)(outF + (size_t)m * HID + n) = make_float2(res[0], res[1]);
                }
            }
        }
    }
}

extern "C" void kernel_launch(void* const* d_in, const int* in_sizes, int n_in,
                              void* d_out, int out_size)
{
    const float* x    = (const float*)d_in[0];
    const float* w_ih = (const float*)d_in[1];
    const float* b_ih = (const float*)d_in[3];
    const float* b_hh = (const float*)d_in[4];
    const float* WH   = (const float*)d_in[5];
    const float* bH   = (const float*)d_in[6];
    const float* WT   = (const float*)d_in[7];
    const float* bT   = (const float*)d_in[8];
    const float* WC   = (const float*)d_in[9];
    const float* bC   = (const float*)d_in[10];
    float* out = (float*)d_out;

    static bool attrSet = false;
    if (!attrSet) {
        cudaFuncSetAttribute(rhn_mma<512, 0, 1>,  cudaFuncAttributeMaxDynamicSharedMemorySize, DSMEM_TOTAL);
        cudaFuncSetAttribute(rhn_mma<1024, 1, 1>, cudaFuncAttributeMaxDynamicSharedMemorySize, DSMEM_TOTAL);
        cudaFuncSetAttribute(rhn_mma<1024, 1, 0>, cudaFuncAttributeMaxDynamicSharedMemorySize, DSMEM_TOTAL);
        attrSet = true;
    }

    __nv_bfloat16 *xh, *xl, *wh, *wl, *WHh, *WHl, *WTh, *WTl, *WCh, *WCl;
    __nv_bfloat16 *hAh, *hAl, *hBh, *hBl;
    cudaGetSymbolAddress((void**)&xh, g_x_hi);   cudaGetSymbolAddress((void**)&xl, g_x_lo);
    cudaGetSymbolAddress((void**)&wh, g_w_hi);   cudaGetSymbolAddress((void**)&wl, g_w_lo);
    cudaGetSymbolAddress((void**)&WHh, g_WH_hi); cudaGetSymbolAddress((void**)&WHl, g_WH_lo);
    cudaGetSymbolAddress((void**)&WTh, g_WT_hi); cudaGetSymbolAddress((void**)&WTl, g_WT_lo);
    cudaGetSymbolAddress((void**)&WCh, g_WC_hi); cudaGetSymbolAddress((void**)&WCl, g_WC_lo);
    cudaGetSymbolAddress((void**)&hAh, g_hA_hi); cudaGetSymbolAddress((void**)&hAl, g_hA_lo);
    cudaGetSymbolAddress((void**)&hBh, g_hB_hi); cudaGetSymbolAddress((void**)&hBl, g_hB_lo);

    // split-precision prep (3 launches)
    {
        int n4 = MROWS * 512 / 4;
        split4<<<(n4 + 255) / 256, 256>>>((const float4*)x, (uint2*)xh, (uint2*)xl, n4);
        n4 = 3 * HID * 512 / 4;
        split4<<<(n4 + 255) / 256, 256>>>((const float4*)w_ih, (uint2*)wh, (uint2*)wl, n4);
        n4 = 5 * HID * HID / 4;
        dim3 g((n4 + 255) / 256, 1, 3);
        split4w<<<g, 256>>>((const float4*)WH, (uint2*)WHh, (uint2*)WHl,
                            (const float4*)WT, (uint2*)WTh, (uint2*)WTl,
                            (const float4*)WC, (uint2*)WCh, (uint2*)WCl, n4);
    }

    dim3 grd(HID / 64, MROWS / 128);
    // GRU gate GEMM (K=512): x -> h (split) into hA
    rhn_mma<512, 0, 1><<<grd, 512, DSMEM_TOTAL>>>(
        xh, xl,
        wh, wl,
        wh + (size_t)HID * 512, wl + (size_t)HID * 512,
        wh + (size_t)2 * HID * 512, wl + (size_t)2 * HID * 512,
        b_ih, b_hh, nullptr, nullptr, nullptr,
        nullptr, hAh, hAl);

    // 5 highway micro-steps
    for (int s = 0; s < 5; s++) {
        size_t wo = (size_t)s * HID * HID;
        const __nv_bfloat16* ih = (s & 1) ? hBh : hAh;
        const __nv_bfloat16* il = (s & 1) ? hBl : hAl;
        __nv_bfloat16* oh = (s & 1) ? hAh : hBh;
        __nv_bfloat16* ol = (s & 1) ? hAl : hBl;
        if (s == 4)
            rhn_mma<1024, 1, 0><<<grd, 512, DSMEM_TOTAL>>>(
                ih, il, WHh + wo, WHl + wo, WTh + wo, WTl + wo, WCh + wo, WCl + wo,
                bH + s * HID, bT + s * HID, bC + s * HID,
                ih, il, out, nullptr, nullptr);
        else
            rhn_mma<1024, 1, 1><<<grd, 512, DSMEM_TOTAL>>>(
                ih, il, WHh + wo, WHl + wo, WTh + wo, WTl + wo, WCh + wo, WCl + wo,
                bH + s * HID, bT + s * HID, bC + s * HID,
                ih, il, nullptr, oh, ol);
    }
}